// round 2
// baseline (speedup 1.0000x reference)
#include <cuda_runtime.h>
#include <cuda_bf16.h>
#include <cstdint>

// Problem constants (fixed by the dataset)
#define BB 16
#define TT 4096
#define CC 128

// Scratch (no cudaMalloc allowed)
__device__ float g_P[CC * CC];    // P = softmax(log_trans, axis=1)
__device__ float g_PT[CC * CC];   // transpose
__device__ float g_beta[(size_t)BB * TT * CC];

#define FMA2(acc, v, p) \
    asm("fma.rn.f32x2 %0, %1, %2, %3;" : "=l"(acc) : "l"(v), "l"(p), "l"(acc))

// ---------------------------------------------------------------------------
// Kernel 1: P = softmax(log_trans, axis=1), plus transpose.
// ---------------------------------------------------------------------------
__global__ void __launch_bounds__(CC) prep_kernel(const float* __restrict__ LT)
{
    const int i = blockIdx.x;
    const int j = threadIdx.x;
    const float v = LT[i * CC + j];

    __shared__ float redm[4];
    __shared__ float reds[4];

    float m = v;
    #pragma unroll
    for (int o = 16; o; o >>= 1) m = fmaxf(m, __shfl_xor_sync(0xffffffffu, m, o));
    if ((j & 31) == 0) redm[j >> 5] = m;
    __syncthreads();
    m = fmaxf(fmaxf(redm[0], redm[1]), fmaxf(redm[2], redm[3]));

    const float e = __expf(v - m);
    float s = e;
    #pragma unroll
    for (int o = 16; o; o >>= 1) s += __shfl_xor_sync(0xffffffffu, s, o);
    if ((j & 31) == 0) reds[j >> 5] = s;
    __syncthreads();
    s = reds[0] + reds[1] + reds[2] + reds[3];

    const float pv = e / s;
    g_P [i * CC + j] = pv;
    g_PT[j * CC + i] = pv;
}

// ---------------------------------------------------------------------------
// Kernel 2: forward/backward scans. 32 blocks (16 fwd + 16 bwd), 128 threads.
// Per step: packed-f32x2 matvec against a register-resident P column,
// single barrier via double-buffered sv + one-step-stale rescale anchor.
//   forward:  alpha_t[j] = u_t[j] + M + log( sum_i exp(alpha_{t-1}[i]-M) P[i][j] )
//   backward: beta_t[i]  =          M + log( sum_j exp(c_j - M) P[i][j] ),
//             c_j = beta_{t+1}[j] + u_{t+1}[j]
// M is the anchor the sv buffer was written with (uniform across threads).
// ---------------------------------------------------------------------------
__global__ void __launch_bounds__(CC, 1) scan_kernel(const float* __restrict__ U,
                                                     float* __restrict__ Alpha)
{
    const int tid = threadIdx.x;
    const int b   = blockIdx.x & 15;
    const bool bwd = blockIdx.x >= 16;

    __shared__ __align__(16) float sv[2][CC];
    __shared__ float sm[2];

    // Register-resident packed matrix column:
    // forward : pair k = (P[2k][tid],  P[2k+1][tid])  = row tid of PT, pairs
    // backward: pair k = (P[tid][2k],  P[tid][2k+1])  = row tid of P,  pairs
    unsigned long long p[CC / 2];
    {
        const float* __restrict__ Mb = bwd ? g_P : g_PT;
        const float2* __restrict__ row = (const float2*)(Mb + (size_t)tid * CC);
        #pragma unroll
        for (int k = 0; k < CC / 2; k++) {
            const float2 f = row[k];
            asm("mov.b64 %0, {%1,%2};" : "=l"(p[k]) : "f"(f.x), "f"(f.y));
        }
    }

    const size_t baseU = (size_t)b * TT * CC;
    const float* __restrict__ Ub = U + baseU;

    // -------- packed matvec: w = dot(svr[0..127], p) --------
    #define MATVEC(svr, w)                                                     \
    {                                                                          \
        unsigned long long a0 = 0ull, a1 = 0ull, a2_ = 0ull, a3 = 0ull;        \
        _Pragma("unroll")                                                      \
        for (int c = 0; c < 32; c += 4) {                                      \
            const ulonglong2 v0 = *(const ulonglong2*)((svr) + 4 * c);         \
            const ulonglong2 v1 = *(const ulonglong2*)((svr) + 4 * c + 4);     \
            const ulonglong2 v2 = *(const ulonglong2*)((svr) + 4 * c + 8);     \
            const ulonglong2 v3 = *(const ulonglong2*)((svr) + 4 * c + 12);    \
            FMA2(a0, v0.x, p[2 * c + 0]);                                      \
            FMA2(a1, v0.y, p[2 * c + 1]);                                      \
            FMA2(a2_, v1.x, p[2 * c + 2]);                                     \
            FMA2(a3, v1.y, p[2 * c + 3]);                                      \
            FMA2(a0, v2.x, p[2 * c + 4]);                                      \
            FMA2(a1, v2.y, p[2 * c + 5]);                                      \
            FMA2(a2_, v3.x, p[2 * c + 6]);                                     \
            FMA2(a3, v3.y, p[2 * c + 7]);                                      \
        }                                                                      \
        float l0, h0, l1, h1, l2, h2, l3, h3;                                  \
        asm("mov.b64 {%0,%1}, %2;" : "=f"(l0), "=f"(h0) : "l"(a0));            \
        asm("mov.b64 {%0,%1}, %2;" : "=f"(l1), "=f"(h1) : "l"(a1));            \
        asm("mov.b64 {%0,%1}, %2;" : "=f"(l2), "=f"(h2) : "l"(a2_));           \
        asm("mov.b64 {%0,%1}, %2;" : "=f"(l3), "=f"(h3) : "l"(a3));            \
        w = ((l0 + h0) + (l1 + h1)) + ((l2 + h2) + (l3 + h3));                 \
    }

    if (!bwd) {
        // ---------------- forward ----------------
        const float a0v = Ub[tid];               // alpha_0
        Alpha[baseU + tid] = a0v;
        float M  = Ub[0];                        // anchor of sv[0] (= alpha_0[0])
        float m1 = M;                            // alpha_{t-1}[0] tracker
        sv[0][tid] = __expf(a0v - M);
        __syncthreads();

        float u_cur = Ub[(size_t)CC + tid];
        const float* svr = sv[0];
        float*       svw = sv[1];
        int nb = 1;
        for (int t = 1; t < TT; ++t) {
            float u_next = 0.0f;
            if (t + 1 < TT) u_next = Ub[(size_t)(t + 1) * CC + tid];

            float w;
            MATVEC(svr, w);

            const float at = u_cur + M + __logf(w);
            Alpha[baseU + (size_t)t * CC + tid] = at;

            svw[tid] = __expf(at - m1);          // anchor m1 (known pre-barrier)
            if (tid == 0) sm[nb] = at;           // broadcast alpha_t[0]
            __syncthreads();

            M = m1;
            m1 = sm[nb];
            const float* tr = svw; svw = (float*)svr; svr = tr;
            nb ^= 1;
            u_cur = u_next;
        }
    } else {
        // ---------------- backward ----------------
        float* __restrict__ Beta = g_beta;
        Beta[baseU + (size_t)(TT - 1) * CC + tid] = 0.0f;

        const float c0 = Ub[(size_t)(TT - 1) * CC + tid];   // c_{T-1} = u_{T-1}
        float M  = Ub[(size_t)(TT - 1) * CC];               // c_{T-1}[0]
        float m1 = M;
        sv[0][tid] = __expf(c0 - M);
        __syncthreads();

        float u_cur = Ub[(size_t)(TT - 2) * CC + tid];
        const float* svr = sv[0];
        float*       svw = sv[1];
        int nb = 1;
        for (int t = TT - 2; t >= 0; --t) {
            float u_next = 0.0f;
            if (t > 0) u_next = Ub[(size_t)(t - 1) * CC + tid];

            float w;
            MATVEC(svr, w);

            const float bt = M + __logf(w);
            Beta[baseU + (size_t)t * CC + tid] = bt;

            const float c2 = bt + u_cur;
            svw[tid] = __expf(c2 - m1);
            if (tid == 0) sm[nb] = c2;
            __syncthreads();

            M = m1;
            m1 = sm[nb];
            const float* tr = svw; svw = (float*)svr; svr = tr;
            nb ^= 1;
            u_cur = u_next;
        }
    }
    #undef MATVEC
}

// ---------------------------------------------------------------------------
// Kernel 3: out = log_softmax(alpha + beta, axis=-1). One warp per (b,t) row.
// ---------------------------------------------------------------------------
__global__ void __launch_bounds__(256) final_kernel(float* __restrict__ Out)
{
    const int warp = blockIdx.x * (blockDim.x >> 5) + (threadIdx.x >> 5);
    const int lane = threadIdx.x & 31;
    const size_t base = (size_t)warp * CC + lane * 4;

    const float4 a4 = *(const float4*)(Out + base);
    const float4 b4 = *(const float4*)(g_beta + base);
    const float s0 = a4.x + b4.x;
    const float s1 = a4.y + b4.y;
    const float s2 = a4.z + b4.z;
    const float s3 = a4.w + b4.w;

    float m = fmaxf(fmaxf(s0, s1), fmaxf(s2, s3));
    #pragma unroll
    for (int o = 16; o; o >>= 1) m = fmaxf(m, __shfl_xor_sync(0xffffffffu, m, o));

    float e = __expf(s0 - m) + __expf(s1 - m) + __expf(s2 - m) + __expf(s3 - m);
    #pragma unroll
    for (int o = 16; o; o >>= 1) e += __shfl_xor_sync(0xffffffffu, e, o);

    const float lse = m + __logf(e);
    float4 o4;
    o4.x = s0 - lse; o4.y = s1 - lse; o4.z = s2 - lse; o4.w = s3 - lse;
    *(float4*)(Out + base) = o4;
}

// ---------------------------------------------------------------------------
// Launch
// ---------------------------------------------------------------------------
extern "C" void kernel_launch(void* const* d_in, const int* in_sizes, int n_in,
                              void* d_out, int out_size)
{
    const float* U  = (const float*)d_in[0];   // unary_logits (B,T,C) fp32
    const float* LT = (const float*)d_in[1];   // log_trans (C,C) fp32
    float* out = (float*)d_out;                // (B,T,C) fp32

    prep_kernel<<<CC, CC>>>(LT);
    scan_kernel<<<2 * BB, CC>>>(U, out);
    final_kernel<<<(BB * TT) / 8, 256>>>(out);
}

// round 3
// speedup vs baseline: 1.0404x; 1.0404x over previous
#include <cuda_runtime.h>
#include <cuda_bf16.h>
#include <cstdint>

// Problem constants (fixed by the dataset)
#define BB 16
#define TT 4096
#define CC 128

// Scratch (no cudaMalloc allowed)
__device__ float g_P[CC * CC];    // P = softmax(log_trans, axis=1)
__device__ float g_PT[CC * CC];   // transpose
__device__ float g_beta[(size_t)BB * TT * CC];

// ---------------------------------------------------------------------------
// Kernel 1: P = softmax(log_trans, axis=1), plus transpose.
// ---------------------------------------------------------------------------
__global__ void __launch_bounds__(CC) prep_kernel(const float* __restrict__ LT)
{
    const int i = blockIdx.x;
    const int j = threadIdx.x;
    const float v = LT[i * CC + j];

    __shared__ float redm[4];
    __shared__ float reds[4];

    float m = v;
    #pragma unroll
    for (int o = 16; o; o >>= 1) m = fmaxf(m, __shfl_xor_sync(0xffffffffu, m, o));
    if ((j & 31) == 0) redm[j >> 5] = m;
    __syncthreads();
    m = fmaxf(fmaxf(redm[0], redm[1]), fmaxf(redm[2], redm[3]));

    const float e = __expf(v - m);
    float s = e;
    #pragma unroll
    for (int o = 16; o; o >>= 1) s += __shfl_xor_sync(0xffffffffu, s, o);
    if ((j & 31) == 0) reds[j >> 5] = s;
    __syncthreads();
    s = reds[0] + reds[1] + reds[2] + reds[3];

    const float pv = e / s;
    g_P [i * CC + j] = pv;
    g_PT[j * CC + i] = pv;
}

// ---------------------------------------------------------------------------
// Kernel 2: forward/backward scans. 32 blocks (16 fwd + 16 bwd), 128 threads.
// Per step (critical path): BAR -> matvec (reg-resident P column vs shared
// exp-state, plain FFMA) -> sum tree -> w*e -> STS -> BAR.
// The log (for the alpha/beta store) happens AFTER the barrier; the exp scale
// factor e = exp(u + M - m1) is computed BEFORE the matvec. One barrier/step
// via double-buffered sv + one-step-stale rescale anchor:
//   sv_next[j] = exp(state_t[j] - m1) = w_j * exp(u_t[j] + M - m1)
// where M = anchor of the sv buffer being read, m1 = state_{t-1}[0].
// ---------------------------------------------------------------------------
__global__ void __launch_bounds__(CC, 1) scan_kernel(const float* __restrict__ U,
                                                     float* __restrict__ Alpha)
{
    const int tid = threadIdx.x;
    const int b   = blockIdx.x & 15;
    const bool bwd = blockIdx.x >= 16;

    __shared__ __align__(16) float sv[2][CC];
    __shared__ float sm[2];

    // Register-resident matrix column:
    // forward : p[i] = P[i][tid]  (thread computes out-state tid, sum over i)
    // backward: p[j] = P[tid][j]  (thread computes state tid, sum over j)
    float p[CC];
    {
        const float* __restrict__ Mb = bwd ? g_P : g_PT;
        const float4* __restrict__ row = (const float4*)(Mb + (size_t)tid * CC);
        #pragma unroll
        for (int k = 0; k < CC / 4; k++) {
            const float4 f = row[k];
            p[4 * k + 0] = f.x; p[4 * k + 1] = f.y;
            p[4 * k + 2] = f.z; p[4 * k + 3] = f.w;
        }
    }

    const size_t baseU = (size_t)b * TT * CC;
    const float* __restrict__ Ub = U + baseU;

    #define MATVEC(svr, w)                                                     \
    {                                                                          \
        float acc0 = 0.f, acc1 = 0.f, acc2 = 0.f, acc3 = 0.f;                  \
        _Pragma("unroll")                                                      \
        for (int i = 0; i < CC; i += 4) {                                      \
            const float4 v4 = *(const float4*)((svr) + i);                     \
            acc0 = fmaf(v4.x, p[i + 0], acc0);                                 \
            acc1 = fmaf(v4.y, p[i + 1], acc1);                                 \
            acc2 = fmaf(v4.z, p[i + 2], acc2);                                 \
            acc3 = fmaf(v4.w, p[i + 3], acc3);                                 \
        }                                                                      \
        w = (acc0 + acc1) + (acc2 + acc3);                                     \
    }

    if (!bwd) {
        // ---------------- forward ----------------
        const float a0v = Ub[tid];               // alpha_0 = u_0
        Alpha[baseU + tid] = a0v;
        float M  = Ub[0];                        // anchor of sv[0] (= alpha_0[0])
        float m1 = M;                            // alpha_{t-1}[0]
        sv[0][tid] = __expf(a0v - M);
        __syncthreads();

        float u_cur = Ub[(size_t)CC + tid];
        const float* svr = sv[0];
        float*       svw = sv[1];
        int nb = 1;
        for (int t = 1; t < TT; ++t) {
            // off-critical-path work first: scale factor + next-u prefetch
            const float shift = u_cur + M - m1;     // uniform-drift-bounded
            const float e = __expf(shift);
            float u_next = 0.0f;
            if (t + 1 < TT) u_next = Ub[(size_t)(t + 1) * CC + tid];

            float w;
            MATVEC(svr, w);

            svw[tid] = w * e;                       // = exp(alpha_t - m1)
            if (tid == 0) sm[nb] = u_cur + M + __logf(w);   // alpha_t[0]
            __syncthreads();

            // alpha_t store: after barrier, hidden under next matvec issue
            Alpha[baseU + (size_t)t * CC + tid] = u_cur + M + __logf(w);

            M = m1;
            m1 = sm[nb];
            const float* tr = svw; svw = (float*)svr; svr = tr;
            nb ^= 1;
            u_cur = u_next;
        }
    } else {
        // ---------------- backward ----------------
        float* __restrict__ Beta = g_beta;
        Beta[baseU + (size_t)(TT - 1) * CC + tid] = 0.0f;

        const float c0 = Ub[(size_t)(TT - 1) * CC + tid];   // c_{T-1} = u_{T-1}
        float M  = Ub[(size_t)(TT - 1) * CC];               // c_{T-1}[0]
        float m1 = M;
        sv[0][tid] = __expf(c0 - M);
        __syncthreads();

        float u_cur = Ub[(size_t)(TT - 2) * CC + tid];
        const float* svr = sv[0];
        float*       svw = sv[1];
        int nb = 1;
        for (int t = TT - 2; t >= 0; --t) {
            // c2 = beta_t + u_t ; sv_next = exp(c2 - m1) = w * exp(M + u_cur - m1)
            const float e = __expf(u_cur + M - m1);
            float u_next = 0.0f;
            if (t > 0) u_next = Ub[(size_t)(t - 1) * CC + tid];

            float w;
            MATVEC(svr, w);

            svw[tid] = w * e;
            if (tid == 0) sm[nb] = M + __logf(w) + u_cur;   // c2[0]
            __syncthreads();

            // beta_t store after barrier (off critical path)
            Beta[baseU + (size_t)t * CC + tid] = M + __logf(w);

            M = m1;
            m1 = sm[nb];
            const float* tr = svw; svw = (float*)svr; svr = tr;
            nb ^= 1;
            u_cur = u_next;
        }
    }
    #undef MATVEC
}

// ---------------------------------------------------------------------------
// Kernel 3: out = log_softmax(alpha + beta, axis=-1). One warp per (b,t) row.
// ---------------------------------------------------------------------------
__global__ void __launch_bounds__(256) final_kernel(float* __restrict__ Out)
{
    const int warp = blockIdx.x * (blockDim.x >> 5) + (threadIdx.x >> 5);
    const int lane = threadIdx.x & 31;
    const size_t base = (size_t)warp * CC + lane * 4;

    const float4 a4 = *(const float4*)(Out + base);
    const float4 b4 = *(const float4*)(g_beta + base);
    const float s0 = a4.x + b4.x;
    const float s1 = a4.y + b4.y;
    const float s2 = a4.z + b4.z;
    const float s3 = a4.w + b4.w;

    float m = fmaxf(fmaxf(s0, s1), fmaxf(s2, s3));
    #pragma unroll
    for (int o = 16; o; o >>= 1) m = fmaxf(m, __shfl_xor_sync(0xffffffffu, m, o));

    float e = __expf(s0 - m) + __expf(s1 - m) + __expf(s2 - m) + __expf(s3 - m);
    #pragma unroll
    for (int o = 16; o; o >>= 1) e += __shfl_xor_sync(0xffffffffu, e, o);

    const float lse = m + __logf(e);
    float4 o4;
    o4.x = s0 - lse; o4.y = s1 - lse; o4.z = s2 - lse; o4.w = s3 - lse;
    *(float4*)(Out + base) = o4;
}

// ---------------------------------------------------------------------------
// Launch
// ---------------------------------------------------------------------------
extern "C" void kernel_launch(void* const* d_in, const int* in_sizes, int n_in,
                              void* d_out, int out_size)
{
    const float* U  = (const float*)d_in[0];   // unary_logits (B,T,C) fp32
    const float* LT = (const float*)d_in[1];   // log_trans (C,C) fp32
    float* out = (float*)d_out;                // (B,T,C) fp32

    prep_kernel<<<CC, CC>>>(LT);
    scan_kernel<<<2 * BB, CC>>>(U, out);
    final_kernel<<<(BB * TT) / 8, 256>>>(out);
}

// round 5
// speedup vs baseline: 1.3468x; 1.2945x over previous
#include <cuda_runtime.h>
#include <cuda_bf16.h>
#include <cstdint>

// Problem constants (fixed by the dataset)
#define BB 16
#define TT 4096
#define CC 128

// Scratch (no cudaMalloc allowed)
__device__ float g_P[CC * CC];    // P = softmax(log_trans, axis=1)
__device__ float g_PT[CC * CC];   // transpose
__device__ float g_beta[(size_t)BB * TT * CC];

// ---------------------------------------------------------------------------
// Kernel 1: P = softmax(log_trans, axis=1), plus transpose.
// ---------------------------------------------------------------------------
__global__ void __launch_bounds__(CC) prep_kernel(const float* __restrict__ LT)
{
    const int i = blockIdx.x;
    const int j = threadIdx.x;
    const float v = LT[i * CC + j];

    __shared__ float redm[4];
    __shared__ float reds[4];

    float m = v;
    #pragma unroll
    for (int o = 16; o; o >>= 1) m = fmaxf(m, __shfl_xor_sync(0xffffffffu, m, o));
    if ((j & 31) == 0) redm[j >> 5] = m;
    __syncthreads();
    m = fmaxf(fmaxf(redm[0], redm[1]), fmaxf(redm[2], redm[3]));

    const float e = __expf(v - m);
    float s = e;
    #pragma unroll
    for (int o = 16; o; o >>= 1) s += __shfl_xor_sync(0xffffffffu, s, o);
    if ((j & 31) == 0) reds[j >> 5] = s;
    __syncthreads();
    s = reds[0] + reds[1] + reds[2] + reds[3];

    const float pv = e / s;
    g_P [i * CC + j] = pv;
    g_PT[j * CC + i] = pv;
}

// 64-length partial dot: shared-vector segment (broadcast LDS.128) against a
// register-resident matrix half-row.
static __device__ __forceinline__ float matvec64(const float* __restrict__ svp,
                                                 const float* __restrict__ p)
{
    float acc0 = 0.f, acc1 = 0.f, acc2 = 0.f, acc3 = 0.f;
    #pragma unroll
    for (int i = 0; i < CC / 2; i += 4) {
        const float4 v4 = *(const float4*)(svp + i);
        acc0 = fmaf(v4.x, p[i + 0], acc0);
        acc1 = fmaf(v4.y, p[i + 1], acc1);
        acc2 = fmaf(v4.z, p[i + 2], acc2);
        acc3 = fmaf(v4.w, p[i + 3], acc3);
    }
    return (acc0 + acc1) + (acc2 + acc3);
}

// ---------------------------------------------------------------------------
// Kernel 2: forward/backward scans. 32 blocks, 256 threads (split-K x2).
// Thread (h=tid>>7, j=tid&127) holds 64 regs of the matrix row and computes a
// 64-length partial dot; partials reduced through shared memory on the first
// of the two per-step barriers. 8 warps/SM (2 per SMSP) for latency hiding.
//   forward:  alpha_t[j] = u_t[j] + M + log( sum_i exp(alpha_{t-1}[i]-M) P[i][j] )
//   backward: beta_t[i]  =          M + log( sum_j exp(c_j - M) P[i][j] )
// sv holds exp(state - anchor); next buffer written as w * exp(u + M - m1)
// (one-step-stale anchor m1 = state_{t-1}[0], numerically validated).
// ---------------------------------------------------------------------------
__global__ void __launch_bounds__(2 * CC, 1) scan_kernel(const float* __restrict__ U,
                                                         float* __restrict__ Alpha)
{
    const int tid = threadIdx.x;
    const int j   = tid & (CC - 1);
    const int h   = tid >> 7;          // 0 or 1
    const int b   = blockIdx.x & 15;
    const bool bwd = blockIdx.x >= 16;

    __shared__ __align__(16) float sv[2][CC];
    __shared__ __align__(16) float spart[2][CC];
    __shared__ float sm[2];

    // 64 matrix registers: forward -> PT row j, half h;  backward -> P row j, half h.
    float p[CC / 2];
    {
        const float* __restrict__ Mb = bwd ? g_P : g_PT;
        const float4* __restrict__ row =
            (const float4*)(Mb + (size_t)j * CC + (h << 6));
        #pragma unroll
        for (int k = 0; k < CC / 8; k++) {
            const float4 f = row[k];
            p[4 * k + 0] = f.x; p[4 * k + 1] = f.y;
            p[4 * k + 2] = f.z; p[4 * k + 3] = f.w;
        }
    }

    const size_t baseU = (size_t)b * TT * CC;
    const float* __restrict__ Ub = U + baseU;

    if (!bwd) {
        // ---------------- forward ----------------
        const float a0v = Ub[j];                 // alpha_0 = u_0
        float m  = Ub[0];                        // anchor of sv[0] (= alpha_0[0])
        float m1 = m;                            // alpha_{t-1}[0]
        if (h == 0) {
            Alpha[baseU + j] = a0v;
            sv[0][j] = __expf(a0v - m);
        }
        __syncthreads();

        float u_cur = Ub[(size_t)CC + j];
        int cur = 0;
        for (int t = 1; t < TT; ++t) {
            const float e = __expf(u_cur + m - m1);     // scale for new sv
            float u_next = 0.0f;
            if (t + 1 < TT) u_next = Ub[(size_t)(t + 1) * CC + j];

            const float part = matvec64(sv[cur] + (h << 6), p);
            spart[h][j] = part;
            __syncthreads();

            const float w = spart[0][j] + spart[1][j];
            if (h == 0) {
                sv[cur ^ 1][j] = w * e;                 // exp(alpha_t - m1)
                Alpha[baseU + (size_t)t * CC + j] = u_cur + m + __logf(w);
            } else if (j == 0) {
                sm[t & 1] = u_cur + m + __logf(w);      // alpha_t[0]
            }
            __syncthreads();

            m = m1;
            m1 = sm[t & 1];
            cur ^= 1;
            u_cur = u_next;
        }
    } else {
        // ---------------- backward ----------------
        float* __restrict__ Beta = g_beta;
        const float c0 = Ub[(size_t)(TT - 1) * CC + j]; // c_{T-1} = u_{T-1}
        float m  = Ub[(size_t)(TT - 1) * CC];           // c_{T-1}[0]
        float m1 = m;
        if (h == 0) {
            Beta[baseU + (size_t)(TT - 1) * CC + j] = 0.0f;
            sv[0][j] = __expf(c0 - m);
        }
        __syncthreads();

        float u_cur = Ub[(size_t)(TT - 2) * CC + j];
        int cur = 0;
        for (int t = TT - 2; t >= 0; --t) {
            const float e = __expf(u_cur + m - m1);
            float u_next = 0.0f;
            if (t > 0) u_next = Ub[(size_t)(t - 1) * CC + j];

            const float part = matvec64(sv[cur] + (h << 6), p);
            spart[h][j] = part;
            __syncthreads();

            const float w = spart[0][j] + spart[1][j];
            if (h == 0) {
                sv[cur ^ 1][j] = w * e;                 // exp(c_t - m1)
                Beta[baseU + (size_t)t * CC + j] = m + __logf(w);
            } else if (j == 0) {
                sm[t & 1] = m + __logf(w) + u_cur;      // c_t[0]
            }
            __syncthreads();

            m = m1;
            m1 = sm[t & 1];
            cur ^= 1;
            u_cur = u_next;
        }
    }
}

// ---------------------------------------------------------------------------
// Kernel 3: out = log_softmax(alpha + beta, axis=-1). One warp per (b,t) row.
// ---------------------------------------------------------------------------
__global__ void __launch_bounds__(256) final_kernel(float* __restrict__ Out)
{
    const int warp = blockIdx.x * (blockDim.x >> 5) + (threadIdx.x >> 5);
    const int lane = threadIdx.x & 31;
    const size_t base = (size_t)warp * CC + lane * 4;

    const float4 a4 = *(const float4*)(Out + base);
    const float4 b4 = *(const float4*)(g_beta + base);
    const float s0 = a4.x + b4.x;
    const float s1 = a4.y + b4.y;
    const float s2 = a4.z + b4.z;
    const float s3 = a4.w + b4.w;

    float m = fmaxf(fmaxf(s0, s1), fmaxf(s2, s3));
    #pragma unroll
    for (int o = 16; o; o >>= 1) m = fmaxf(m, __shfl_xor_sync(0xffffffffu, m, o));

    float e = __expf(s0 - m) + __expf(s1 - m) + __expf(s2 - m) + __expf(s3 - m);
    #pragma unroll
    for (int o = 16; o; o >>= 1) e += __shfl_xor_sync(0xffffffffu, e, o);

    const float lse = m + __logf(e);
    float4 o4;
    o4.x = s0 - lse; o4.y = s1 - lse; o4.z = s2 - lse; o4.w = s3 - lse;
    *(float4*)(Out + base) = o4;
}

// ---------------------------------------------------------------------------
// Launch
// ---------------------------------------------------------------------------
extern "C" void kernel_launch(void* const* d_in, const int* in_sizes, int n_in,
                              void* d_out, int out_size)
{
    const float* U  = (const float*)d_in[0];   // unary_logits (B,T,C) fp32
    const float* LT = (const float*)d_in[1];   // log_trans (C,C) fp32
    float* out = (float*)d_out;                // (B,T,C) fp32

    prep_kernel<<<CC, CC>>>(LT);
    scan_kernel<<<2 * BB, 2 * CC>>>(U, out);
    final_kernel<<<(BB * TT) / 8, 256>>>(out);
}